// round 2
// baseline (speedup 1.0000x reference)
#include <cuda_runtime.h>
#include <cstdint>
#include <cstddef>

#define NB      2
#define LQ      2048
#define LK      2048
#define DMODEL  1024
#define DK      64
#define DHEAD   16
#define DEPTH   1024
#define MROWS   (NB * LQ)   // 4096

// Scratch buffers (allocation-free rule: __device__ globals).
// Device code references these directly — no cudaGetSymbolAddress on host.
__device__ float g_Q[(size_t)MROWS * DEPTH];
__device__ float g_K[(size_t)MROWS * DEPTH];
__device__ float g_V[(size_t)MROWS * DEPTH];
__device__ float g_O[(size_t)MROWS * DEPTH];

// ---------------------------------------------------------------------------
// GEMM: C[M,1024] = A[M,1024] @ W[1024,1024] + bias
// 128x128 tile, BK=16, 256 threads, 8x8 per-thread micro tile, fp32.
// a_sel: 0 = use A param, 1 = g_O
// c_sel: 0 = g_Q, 1 = g_K, 2 = g_V, 3 = use C param
// ---------------------------------------------------------------------------
__global__ __launch_bounds__(256) void gemm_bias_kernel(
    const float* __restrict__ Ain, const float* __restrict__ W,
    const float* __restrict__ bias, float* __restrict__ Cout,
    int a_sel, int c_sel)
{
    const float* A = (a_sel == 1) ? (const float*)g_O : Ain;
    float* C;
    switch (c_sel) {
        case 0:  C = g_Q;  break;
        case 1:  C = g_K;  break;
        case 2:  C = g_V;  break;
        default: C = Cout; break;
    }

    __shared__ float As[16][128];
    __shared__ float Bs[16][128];

    const int tid = threadIdx.x;
    const int tx = tid & 15;          // 0..15 (N dir)
    const int ty = tid >> 4;          // 0..15 (M dir)
    const int m0 = blockIdx.y * 128;
    const int n0 = blockIdx.x * 128;

    float acc[8][8];
#pragma unroll
    for (int i = 0; i < 8; i++)
#pragma unroll
        for (int j = 0; j < 8; j++) acc[i][j] = 0.f;

    for (int k0 = 0; k0 < DMODEL; k0 += 16) {
        // Load A tile (128 rows x 16 k), store transposed: As[k][m]
#pragma unroll
        for (int i = 0; i < 2; i++) {
            int c = tid * 2 + i;              // 0..511 (chunks of 4 floats)
            int r = c >> 2;                   // 0..127
            int kk = (c & 3) * 4;             // 0,4,8,12
            float4 v = *(const float4*)&A[(size_t)(m0 + r) * DMODEL + k0 + kk];
            As[kk + 0][r] = v.x; As[kk + 1][r] = v.y;
            As[kk + 2][r] = v.z; As[kk + 3][r] = v.w;
        }
        // Load B tile (16 k rows x 128 cols)
#pragma unroll
        for (int i = 0; i < 2; i++) {
            int c = tid * 2 + i;              // 0..511
            int r = c >> 5;                   // 0..15
            int nn = (c & 31) * 4;            // 0..124
            *(float4*)&Bs[r][nn] =
                *(const float4*)&W[(size_t)(k0 + r) * DEPTH + n0 + nn];
        }
        __syncthreads();

#pragma unroll
        for (int kk = 0; kk < 16; kk++) {
            float a[8], b[8];
            float4 a0 = *(const float4*)&As[kk][ty * 8];
            float4 a1 = *(const float4*)&As[kk][ty * 8 + 4];
            float4 b0 = *(const float4*)&Bs[kk][tx * 8];
            float4 b1 = *(const float4*)&Bs[kk][tx * 8 + 4];
            a[0]=a0.x; a[1]=a0.y; a[2]=a0.z; a[3]=a0.w;
            a[4]=a1.x; a[5]=a1.y; a[6]=a1.z; a[7]=a1.w;
            b[0]=b0.x; b[1]=b0.y; b[2]=b0.z; b[3]=b0.w;
            b[4]=b1.x; b[5]=b1.y; b[6]=b1.z; b[7]=b1.w;
#pragma unroll
            for (int i = 0; i < 8; i++)
#pragma unroll
                for (int j = 0; j < 8; j++)
                    acc[i][j] = fmaf(a[i], b[j], acc[i][j]);
        }
        __syncthreads();
    }

    // Epilogue: + bias
#pragma unroll
    for (int i = 0; i < 8; i++) {
        int row = m0 + ty * 8 + i;
#pragma unroll
        for (int j = 0; j < 8; j += 4) {
            int col = n0 + tx * 8 + j;
            float4 bv = *(const float4*)&bias[col];
            float4 r;
            r.x = acc[i][j + 0] + bv.x;
            r.y = acc[i][j + 1] + bv.y;
            r.z = acc[i][j + 2] + bv.z;
            r.w = acc[i][j + 3] + bv.w;
            *(float4*)&C[(size_t)row * DEPTH + col] = r;
        }
    }
}

// ---------------------------------------------------------------------------
// Flash attention (causal), fp32. One CTA = 128 query rows of one (b, h).
// Each thread owns one query row: q[64] and o[64] in registers.
// K/V tiles (64 x 64) staged in smem; broadcast float4 reads.
// Reads g_Q/g_K/g_V, writes g_O (direct global references).
// ---------------------------------------------------------------------------
__global__ __launch_bounds__(128) void flash_attn_kernel()
{
    const int qt = blockIdx.x;       // q tile (0..15)
    const int h  = blockIdx.y;       // head
    const int b  = blockIdx.z;       // batch
    const int t  = threadIdx.x;      // 0..127
    const int qr = qt * 128 + t;     // global query row within sequence

    const float fac = 0.125f;        // 1/sqrt(64)

    __shared__ float Ks[64][64];
    __shared__ float Vs[64][64];

    float q[64];
    {
        const float* qp = g_Q + ((size_t)(b * LQ + qr) * DEPTH) + h * DK;
#pragma unroll
        for (int i = 0; i < 16; i++) {
            float4 v = *(const float4*)&qp[i * 4];
            q[i * 4 + 0] = v.x * fac;
            q[i * 4 + 1] = v.y * fac;
            q[i * 4 + 2] = v.z * fac;
            q[i * 4 + 3] = v.w * fac;
        }
    }

    float o[64];
#pragma unroll
    for (int d = 0; d < 64; d++) o[d] = 0.f;
    float m = -1e30f, l = 0.f;

    const int kmax = qt * 128 + 127;     // largest valid key for this block
    const int ntiles = kmax / 64 + 1;

    for (int kt = 0; kt < ntiles; kt++) {
        const int k0 = kt * 64;
        __syncthreads();
        {
            // Each thread loads half a row (32 floats) of K and V
            int r  = t >> 1;
            int c0 = (t & 1) * 32;
            const float* kp = g_K + ((size_t)(b * LK + k0 + r) * DEPTH) + h * DK + c0;
            const float* vp = g_V + ((size_t)(b * LK + k0 + r) * DEPTH) + h * DK + c0;
#pragma unroll
            for (int i = 0; i < 8; i++) {
                *(float4*)&Ks[r][c0 + i * 4] = *(const float4*)&kp[i * 4];
                *(float4*)&Vs[r][c0 + i * 4] = *(const float4*)&vp[i * 4];
            }
        }
        __syncthreads();

#pragma unroll 1
        for (int jc = 0; jc < 64; jc += 8) {
            float s[8];
#pragma unroll
            for (int jj = 0; jj < 8; jj++) {
                float accv = 0.f;
                const float4* kr = (const float4*)&Ks[jc + jj][0];
#pragma unroll
                for (int d4 = 0; d4 < 16; d4++) {
                    float4 kv = kr[d4];
                    accv = fmaf(q[d4 * 4 + 0], kv.x, accv);
                    accv = fmaf(q[d4 * 4 + 1], kv.y, accv);
                    accv = fmaf(q[d4 * 4 + 2], kv.z, accv);
                    accv = fmaf(q[d4 * 4 + 3], kv.w, accv);
                }
                int kcol = k0 + jc + jj;
                s[jj] = (kcol <= qr) ? accv : -1e30f;
            }
            // chunk max
            float mt = s[0];
#pragma unroll
            for (int jj = 1; jj < 8; jj++) mt = fmaxf(mt, s[jj]);
            float mnew = fmaxf(m, mt);
            float corr = __expf(m - mnew);
            l *= corr;
#pragma unroll
            for (int d = 0; d < 64; d++) o[d] *= corr;
            m = mnew;
#pragma unroll
            for (int jj = 0; jj < 8; jj++) {
                float p = __expf(s[jj] - mnew);
                l += p;
                const float4* vr = (const float4*)&Vs[jc + jj][0];
#pragma unroll
                for (int d4 = 0; d4 < 16; d4++) {
                    float4 vv = vr[d4];
                    o[d4 * 4 + 0] = fmaf(p, vv.x, o[d4 * 4 + 0]);
                    o[d4 * 4 + 1] = fmaf(p, vv.y, o[d4 * 4 + 1]);
                    o[d4 * 4 + 2] = fmaf(p, vv.z, o[d4 * 4 + 2]);
                    o[d4 * 4 + 3] = fmaf(p, vv.w, o[d4 * 4 + 3]);
                }
            }
        }
    }

    float inv = 1.f / l;
    float* op = g_O + ((size_t)(b * LQ + qr) * DEPTH) + h * DK;
#pragma unroll
    for (int i = 0; i < 16; i++) {
        float4 r;
        r.x = o[i * 4 + 0] * inv;
        r.y = o[i * 4 + 1] * inv;
        r.z = o[i * 4 + 2] * inv;
        r.w = o[i * 4 + 3] * inv;
        *(float4*)&op[i * 4] = r;
    }
}

// ---------------------------------------------------------------------------
// Launch: pure kernel launches, nothing else (graph-capture-safe).
// ---------------------------------------------------------------------------
extern "C" void kernel_launch(void* const* d_in, const int* in_sizes, int n_in,
                              void* d_out, int out_size)
{
    const float* x  = (const float*)d_in[0];
    const float* y  = (const float*)d_in[1];
    // d_in[2] = mask (causal tril) — implicit in kernel
    const float* Wq = (const float*)d_in[3];
    const float* bq = (const float*)d_in[4];
    const float* Wk = (const float*)d_in[5];
    const float* bk = (const float*)d_in[6];
    const float* Wv = (const float*)d_in[7];
    const float* bv = (const float*)d_in[8];
    const float* Wo = (const float*)d_in[9];
    const float* bo = (const float*)d_in[10];
    float* out = (float*)d_out;

    dim3 ggrid(DEPTH / 128, MROWS / 128);   // (8, 32)
    gemm_bias_kernel<<<ggrid, 256>>>(x, Wq, bq, nullptr, 0, 0);  // -> g_Q
    gemm_bias_kernel<<<ggrid, 256>>>(y, Wk, bk, nullptr, 0, 1);  // -> g_K
    gemm_bias_kernel<<<ggrid, 256>>>(y, Wv, bv, nullptr, 0, 2);  // -> g_V

    dim3 agrid(LQ / 128, DHEAD, NB);        // (16, 16, 2)
    flash_attn_kernel<<<agrid, 128>>>();    // g_Q,g_K,g_V -> g_O

    gemm_bias_kernel<<<ggrid, 256>>>(nullptr, Wo, bo, out, 1, 3);  // g_O -> out
}

// round 6
// speedup vs baseline: 1.0859x; 1.0859x over previous
#include <cuda_runtime.h>
#include <cstdint>
#include <cstddef>

#define NB      2
#define LQ      2048
#define LK      2048
#define DMODEL  1024
#define DK      64
#define DHEAD   16
#define DEPTH   1024
#define MROWS   4096

// Scratch (__device__ globals; allocation-free rule)
__device__ float g_Q[(size_t)MROWS * DEPTH];
__device__ float g_K[(size_t)MROWS * DEPTH];
__device__ float g_V[(size_t)MROWS * DEPTH];
__device__ float g_O[(size_t)MROWS * DEPTH];
__device__ float g_Xc[(size_t)MROWS * DMODEL];        // tf32-rounded x
__device__ float g_Yc[(size_t)MROWS * DMODEL];        // tf32-rounded y
__device__ float g_Wc[4][(size_t)DMODEL * DEPTH];     // tf32-rounded W (native [k][n])

// ---------------------------------------------------------------------------
// Helpers
// ---------------------------------------------------------------------------
__device__ __forceinline__ uint32_t smem_u32(const void* p) {
    uint32_t a;
    asm("{ .reg .u64 t; cvta.to.shared.u64 t, %1; cvt.u32.u64 %0, t; }"
        : "=r"(a) : "l"(p));
    return a;
}
__device__ __forceinline__ float rna_tf32(float x) {
    float r; asm("cvt.rna.tf32.f32 %0, %1;" : "=f"(r) : "f"(x)); return r;
}
__device__ __forceinline__ void cp16(uint32_t dst, const void* src) {
    asm volatile("cp.async.cg.shared.global [%0], [%1], 16;" :: "r"(dst), "l"(src));
}
__device__ __forceinline__ void cp_commit() { asm volatile("cp.async.commit_group;"); }
__device__ __forceinline__ void cp_wait1()  { asm volatile("cp.async.wait_group 1;" ::: "memory"); }
__device__ __forceinline__ void cp_wait0()  { asm volatile("cp.async.wait_group 0;" ::: "memory"); }

// m16n8k8 tf32 mma: D = A*B + D
__device__ __forceinline__ void mma_tf32(float& c0, float& c1, float& c2, float& c3,
                                         uint32_t a0, uint32_t a1, uint32_t a2, uint32_t a3,
                                         uint32_t b0, uint32_t b1) {
    asm volatile("mma.sync.aligned.m16n8k8.row.col.f32.tf32.tf32.f32 "
                 "{%0,%1,%2,%3}, {%4,%5,%6,%7}, {%8,%9}, {%0,%1,%2,%3};"
                 : "+f"(c0), "+f"(c1), "+f"(c2), "+f"(c3)
                 : "r"(a0), "r"(a1), "r"(a2), "r"(a3), "r"(b0), "r"(b1));
}

// ---------------------------------------------------------------------------
// Pre-pass: tf32-round x/y (sel 0/1) or W (sel 2..5 -> g_Wc[sel-2])
// ---------------------------------------------------------------------------
__global__ __launch_bounds__(256) void round_copy_kernel(const float* __restrict__ in, int sel) {
    float* out;
    switch (sel) {
        case 0: out = g_Xc; break;
        case 1: out = g_Yc; break;
        default: out = g_Wc[sel - 2]; break;
    }
    size_t i = (size_t)blockIdx.x * 256 + threadIdx.x;
    float4 v = ((const float4*)in)[i];
    v.x = rna_tf32(v.x); v.y = rna_tf32(v.y);
    v.z = rna_tf32(v.z); v.w = rna_tf32(v.w);
    ((float4*)out)[i] = v;
}

// ---------------------------------------------------------------------------
// tf32 mma.sync GEMM: C[4096,1024] = A[4096,1024] @ W[1024,1024] + bias
// CTA: 128x128 tile, 256 thr (8 warps, each 64x32). BK=32, double-buffered
// cp.async. Smem A: [m][36] (pad), B: [k][132] (pad) — conflict-free frags.
// a_sel: 0=g_Xc 1=g_Yc 2=g_O ; c_sel: 0=g_Q 1=g_K 2=g_V 3=Cout
// ---------------------------------------------------------------------------
#define PADA 36
#define PADB 132
#define ABUF (128 * PADA)            // 4608 floats
#define BBUF (32 * PADB)             // 4224 floats
#define GEMM_SMEM ((2 * ABUF + 2 * BBUF) * 4)   // 70656 bytes

__global__ __launch_bounds__(256) void gemm_tc_kernel(
    const float* __restrict__ bias, float* __restrict__ Cout,
    int a_sel, int widx, int c_sel)
{
    extern __shared__ float sm[];
    const float* A = (a_sel == 0) ? g_Xc : (a_sel == 1) ? g_Yc : g_O;
    const float* B = g_Wc[widx];
    float* C;
    switch (c_sel) { case 0: C = g_Q; break; case 1: C = g_K; break;
                     case 2: C = g_V; break; default: C = Cout; break; }

    float* As = sm;                   // 2 x ABUF
    float* Bs = sm + 2 * ABUF;        // 2 x BBUF
    const uint32_t As_u = smem_u32(As), Bs_u = smem_u32(Bs);

    const int tid = threadIdx.x;
    const int wid = tid >> 5, lane = tid & 31;
    const int gid = lane >> 2, tig = lane & 3;
    const int wr = wid >> 2, wc = wid & 3;     // warp row (0..1), warp col (0..3)
    const int m0 = blockIdx.y * 128, n0 = blockIdx.x * 128;

    // A load mapping: 2 threads per row, 4 segs each
    const int am  = tid >> 1;                  // 0..127
    const int ah  = (tid & 1) * 16;            // float offset 0 / 16
    // B load mapping: 8 threads per k-row, 4 segs each
    const int bk  = tid >> 3;                  // 0..31
    const int bn  = (tid & 7) * 16;            // float offset

    const float* Arow = A + (size_t)(m0 + am) * DMODEL + ah;
    const float* Bcol = B + (size_t)bk * DEPTH + n0 + bn;

#define LOAD_CHUNK(c) do {                                                     \
        int _s = (c) & 1;                                                      \
        uint32_t _ad = As_u + (uint32_t)(_s * ABUF + am * PADA + ah) * 4;      \
        uint32_t _bd = Bs_u + (uint32_t)(_s * BBUF + bk * PADB + bn) * 4;      \
        const float* _ap = Arow + (c) * 32;                                    \
        const float* _bp = Bcol + (size_t)(c) * 32 * DEPTH;                    \
        _Pragma("unroll")                                                      \
        for (int _i = 0; _i < 4; _i++) {                                       \
            cp16(_ad + _i * 16, _ap + _i * 4);                                 \
            cp16(_bd + _i * 16, _bp + _i * 4);                                 \
        }                                                                      \
    } while (0)

    float c[4][4][4];   // [mt][nt][reg]
#pragma unroll
    for (int mt = 0; mt < 4; mt++)
#pragma unroll
        for (int nt = 0; nt < 4; nt++)
#pragma unroll
            for (int r = 0; r < 4; r++) c[mt][nt][r] = 0.f;

    LOAD_CHUNK(0);
    cp_commit();

#pragma unroll 1
    for (int ch = 0; ch < 32; ch++) {
        if (ch + 1 < 32) {
            LOAD_CHUNK(ch + 1);
            cp_commit();
            cp_wait1();
        } else {
            cp_wait0();
        }
        __syncthreads();

        const float* Ab = As + (ch & 1) * ABUF;
        const float* Bb = Bs + (ch & 1) * BBUF;
#pragma unroll
        for (int ks = 0; ks < 4; ks++) {
            const int k0 = ks * 8;
            uint32_t a[4][4], b[4][2];
#pragma unroll
            for (int mt = 0; mt < 4; mt++) {
                const float* ap = Ab + (wr * 64 + mt * 16 + gid) * PADA + k0 + tig;
                a[mt][0] = __float_as_uint(ap[0]);
                a[mt][1] = __float_as_uint(ap[8 * PADA]);
                a[mt][2] = __float_as_uint(ap[4]);
                a[mt][3] = __float_as_uint(ap[8 * PADA + 4]);
            }
#pragma unroll
            for (int nt = 0; nt < 4; nt++) {
                const float* bp = Bb + (k0 + tig) * PADB + wc * 32 + nt * 8 + gid;
                b[nt][0] = __float_as_uint(bp[0]);
                b[nt][1] = __float_as_uint(bp[4 * PADB]);
            }
#pragma unroll
            for (int mt = 0; mt < 4; mt++)
#pragma unroll
                for (int nt = 0; nt < 4; nt++)
                    mma_tf32(c[mt][nt][0], c[mt][nt][1], c[mt][nt][2], c[mt][nt][3],
                             a[mt][0], a[mt][1], a[mt][2], a[mt][3],
                             b[nt][0], b[nt][1]);
        }
        __syncthreads();
    }
#undef LOAD_CHUNK

    // Epilogue: c0,c1 -> (row, col..col+1); c2,c3 -> (row+8, ...)
#pragma unroll
    for (int mt = 0; mt < 4; mt++) {
        const int row = m0 + wr * 64 + mt * 16 + gid;
#pragma unroll
        for (int nt = 0; nt < 4; nt++) {
            const int col = n0 + wc * 32 + nt * 8 + tig * 2;
            float2 bv = *(const float2*)&bias[col];
            float2 r0, r1;
            r0.x = c[mt][nt][0] + bv.x; r0.y = c[mt][nt][1] + bv.y;
            r1.x = c[mt][nt][2] + bv.x; r1.y = c[mt][nt][3] + bv.y;
            *(float2*)&C[(size_t)row * DEPTH + col] = r0;
            *(float2*)&C[(size_t)(row + 8) * DEPTH + col] = r1;
        }
    }
}

// ---------------------------------------------------------------------------
// Flash attention (causal), fp32, split-dk: 256 threads / 128 q rows.
// Thread pair (2r, 2r+1) shares row r: each half owns 32 of the 64 dims.
// Output rounded to tf32 (feeds the tf32 O-projection GEMM).
// ---------------------------------------------------------------------------
__global__ __launch_bounds__(256) void flash_attn_kernel()
{
    const int qt = blockIdx.x, h = blockIdx.y, b = blockIdx.z;
    const int t = threadIdx.x;
    const int rl = t >> 1, half = t & 1;
    const int qr = qt * 128 + rl;
    const float fac = 0.125f;

    __shared__ float Ks[64][64];
    __shared__ float Vs[64][64];

    float q[32];
    {
        const float* qp = g_Q + (size_t)(b * LQ + qr) * DEPTH + h * DK + half * 32;
#pragma unroll
        for (int i = 0; i < 8; i++) {
            float4 v = *(const float4*)&qp[i * 4];
            q[i * 4 + 0] = v.x * fac; q[i * 4 + 1] = v.y * fac;
            q[i * 4 + 2] = v.z * fac; q[i * 4 + 3] = v.w * fac;
        }
    }
    float o[32];
#pragma unroll
    for (int d = 0; d < 32; d++) o[d] = 0.f;
    float m = -1e30f, l = 0.f;

    const int ntiles = 2 * qt + 2;

#pragma unroll 1
    for (int kt = 0; kt < ntiles; kt++) {
        const int k0 = kt * 64;
        __syncthreads();
#pragma unroll
        for (int i = 0; i < 4; i++) {
            int idx = i * 256 + t;
            int r = idx >> 4, c4 = idx & 15;
            size_t base = (size_t)(b * LK + k0 + r) * DEPTH + h * DK + c4 * 4;
            *(float4*)&Ks[r][c4 * 4] = *(const float4*)&g_K[base];
            *(float4*)&Vs[r][c4 * 4] = *(const float4*)&g_V[base];
        }
        __syncthreads();

#pragma unroll 1
        for (int jc = 0; jc < 64; jc += 8) {
            float s[8];
#pragma unroll
            for (int jj = 0; jj < 8; jj++) {
                float acc = 0.f;
                const float4* kr = (const float4*)&Ks[jc + jj][half * 32];
#pragma unroll
                for (int d4 = 0; d4 < 8; d4++) {
                    float4 kv = kr[d4];
                    acc = fmaf(q[d4 * 4 + 0], kv.x, acc);
                    acc = fmaf(q[d4 * 4 + 1], kv.y, acc);
                    acc = fmaf(q[d4 * 4 + 2], kv.z, acc);
                    acc = fmaf(q[d4 * 4 + 3], kv.w, acc);
                }
                s[jj] = acc;
            }
#pragma unroll
            for (int jj = 0; jj < 8; jj++) {
                s[jj] += __shfl_xor_sync(0xffffffffu, s[jj], 1);
                int kcol = k0 + jc + jj;
                if (kcol > qr) s[jj] = -1e30f;
            }
            float mt = s[0];
#pragma unroll
            for (int jj = 1; jj < 8; jj++) mt = fmaxf(mt, s[jj]);
            float mnew = fmaxf(m, mt);
            float corr = __expf(m - mnew);
            l *= corr;
#pragma unroll
            for (int d = 0; d < 32; d++) o[d] *= corr;
            m = mnew;
#pragma unroll
            for (int jj = 0; jj < 8; jj++) {
                float p = __expf(s[jj] - mnew);
                l += p;
                const float4* vr = (const float4*)&Vs[jc + jj][half * 32];
#pragma unroll
                for (int d4 = 0; d4 < 8; d4++) {
                    float4 vv = vr[d4];
                    o[d4 * 4 + 0] = fmaf(p, vv.x, o[d4 * 4 + 0]);
                    o[d4 * 4 + 1] = fmaf(p, vv.y, o[d4 * 4 + 1]);
                    o[d4 * 4 + 2] = fmaf(p, vv.z, o[d4 * 4 + 2]);
                    o[d4 * 4 + 3] = fmaf(p, vv.w, o[d4 * 4 + 3]);
                }
            }
        }
    }

    const float inv = 1.f / l;
    float* op = g_O + (size_t)(b * LQ + qr) * DEPTH + h * DK + half * 32;
#pragma unroll
    for (int i = 0; i < 8; i++) {
        float4 r;
        r.x = rna_tf32(o[i * 4 + 0] * inv);
        r.y = rna_tf32(o[i * 4 + 1] * inv);
        r.z = rna_tf32(o[i * 4 + 2] * inv);
        r.w = rna_tf32(o[i * 4 + 3] * inv);
        *(float4*)&op[i * 4] = r;
    }
}

// ---------------------------------------------------------------------------
// Launch
// ---------------------------------------------------------------------------
extern "C" void kernel_launch(void* const* d_in, const int* in_sizes, int n_in,
                              void* d_out, int out_size)
{
    const float* x  = (const float*)d_in[0];
    const float* y  = (const float*)d_in[1];
    // d_in[2] = mask (causal) — implicit
    const float* Wq = (const float*)d_in[3];
    const float* bq = (const float*)d_in[4];
    const float* Wk = (const float*)d_in[5];
    const float* bk = (const float*)d_in[6];
    const float* Wv = (const float*)d_in[7];
    const float* bv = (const float*)d_in[8];
    const float* Wo = (const float*)d_in[9];
    const float* bo = (const float*)d_in[10];
    float* out = (float*)d_out;

    cudaFuncSetAttribute(gemm_tc_kernel,
                         cudaFuncAttributeMaxDynamicSharedMemorySize, GEMM_SMEM);

    round_copy_kernel<<<4096, 256>>>(x, 0);
    round_copy_kernel<<<4096, 256>>>(y, 1);
    round_copy_kernel<<<1024, 256>>>(Wq, 2);
    round_copy_kernel<<<1024, 256>>>(Wk, 3);
    round_copy_kernel<<<1024, 256>>>(Wv, 4);
    round_copy_kernel<<<1024, 256>>>(Wo, 5);

    dim3 ggrid(DEPTH / 128, MROWS / 128);   // (8, 32)
    gemm_tc_kernel<<<ggrid, 256, GEMM_SMEM>>>(bq, nullptr, 0, 0, 0);  // x @ Wq -> g_Q
    gemm_tc_kernel<<<ggrid, 256, GEMM_SMEM>>>(bk, nullptr, 1, 1, 1);  // y @ Wk -> g_K
    gemm_tc_kernel<<<ggrid, 256, GEMM_SMEM>>>(bv, nullptr, 1, 2, 2);  // y @ Wv -> g_V

    dim3 agrid(LQ / 128, DHEAD, NB);        // (16, 16, 2)
    flash_attn_kernel<<<agrid, 256>>>();    // -> g_O (tf32-rounded)

    gemm_tc_kernel<<<ggrid, 256, GEMM_SMEM>>>(bo, out, 2, 3, 3);      // g_O @ Wo -> out
}

// round 7
// speedup vs baseline: 2.8503x; 2.6249x over previous
#include <cuda_runtime.h>
#include <cstdint>
#include <cstddef>

#define NB      2
#define LQ      2048
#define LK      2048
#define DMODEL  1024
#define DK      64
#define DHEAD   16
#define DEPTH   1024
#define MROWS   4096

// Scratch (__device__ globals; allocation-free rule)
__device__ float g_Q[(size_t)MROWS * DEPTH];
__device__ float g_K[(size_t)MROWS * DEPTH];   // tf32-rounded at GEMM epilogue
__device__ float g_V[(size_t)MROWS * DEPTH];   // tf32-rounded at GEMM epilogue
__device__ float g_O[(size_t)MROWS * DEPTH];   // tf32-rounded at attention epilogue
__device__ float g_Xc[(size_t)MROWS * DMODEL];
__device__ float g_Yc[(size_t)MROWS * DMODEL];
__device__ float g_Wc[4][(size_t)DMODEL * DEPTH];

// ---------------------------------------------------------------------------
// Helpers
// ---------------------------------------------------------------------------
__device__ __forceinline__ uint32_t smem_u32(const void* p) {
    uint32_t a;
    asm("{ .reg .u64 t; cvta.to.shared.u64 t, %1; cvt.u32.u64 %0, t; }"
        : "=r"(a) : "l"(p));
    return a;
}
__device__ __forceinline__ float rna_tf32(float x) {
    float r; asm("cvt.rna.tf32.f32 %0, %1;" : "=f"(r) : "f"(x)); return r;
}
__device__ __forceinline__ void cp16(uint32_t dst, const void* src) {
    asm volatile("cp.async.cg.shared.global [%0], [%1], 16;" :: "r"(dst), "l"(src));
}
__device__ __forceinline__ void cp_commit() { asm volatile("cp.async.commit_group;"); }
__device__ __forceinline__ void cp_wait1()  { asm volatile("cp.async.wait_group 1;" ::: "memory"); }
__device__ __forceinline__ void cp_wait0()  { asm volatile("cp.async.wait_group 0;" ::: "memory"); }

// m16n8k8 tf32 mma: D = A*B + D
__device__ __forceinline__ void mma_tf32(float& c0, float& c1, float& c2, float& c3,
                                         uint32_t a0, uint32_t a1, uint32_t a2, uint32_t a3,
                                         uint32_t b0, uint32_t b1) {
    asm volatile("mma.sync.aligned.m16n8k8.row.col.f32.tf32.tf32.f32 "
                 "{%0,%1,%2,%3}, {%4,%5,%6,%7}, {%8,%9}, {%0,%1,%2,%3};"
                 : "+f"(c0), "+f"(c1), "+f"(c2), "+f"(c3)
                 : "r"(a0), "r"(a1), "r"(a2), "r"(a3), "r"(b0), "r"(b1));
}

// ---------------------------------------------------------------------------
// Prepass: tf32-round x/y (one launch) and the 4 W's (one launch)
// ---------------------------------------------------------------------------
__global__ __launch_bounds__(256) void round_xy_kernel(const float* __restrict__ x,
                                                       const float* __restrict__ y) {
    const float* in = blockIdx.y ? y : x;
    float* out = blockIdx.y ? g_Yc : g_Xc;
    size_t i = (size_t)blockIdx.x * 256 + threadIdx.x;
    float4 v = ((const float4*)in)[i];
    v.x = rna_tf32(v.x); v.y = rna_tf32(v.y);
    v.z = rna_tf32(v.z); v.w = rna_tf32(v.w);
    ((float4*)out)[i] = v;
}
__global__ __launch_bounds__(256) void round_w_kernel(const float* __restrict__ w0,
                                                      const float* __restrict__ w1,
                                                      const float* __restrict__ w2,
                                                      const float* __restrict__ w3) {
    const float* in;
    switch (blockIdx.y) { case 0: in = w0; break; case 1: in = w1; break;
                          case 2: in = w2; break; default: in = w3; break; }
    float* out = g_Wc[blockIdx.y];
    size_t i = (size_t)blockIdx.x * 256 + threadIdx.x;
    float4 v = ((const float4*)in)[i];
    v.x = rna_tf32(v.x); v.y = rna_tf32(v.y);
    v.z = rna_tf32(v.z); v.w = rna_tf32(v.w);
    ((float4*)out)[i] = v;
}

// ---------------------------------------------------------------------------
// tf32 mma.sync GEMM (as R6): C[4096,1024] = A @ W + bias.
// K/V outputs tf32-rounded in epilogue (exact inputs for attention mma).
// ---------------------------------------------------------------------------
#define PADA 36
#define PADB 132
#define ABUF (128 * PADA)
#define BBUF (32 * PADB)
#define GEMM_SMEM ((2 * ABUF + 2 * BBUF) * 4)

__global__ __launch_bounds__(256) void gemm_tc_kernel(
    const float* __restrict__ bias, float* __restrict__ Cout,
    int a_sel, int widx, int c_sel)
{
    extern __shared__ float sm[];
    const float* A = (a_sel == 0) ? g_Xc : (a_sel == 1) ? g_Yc : g_O;
    const float* B = g_Wc[widx];
    float* C;
    switch (c_sel) { case 0: C = g_Q; break; case 1: C = g_K; break;
                     case 2: C = g_V; break; default: C = Cout; break; }

    float* As = sm;
    float* Bs = sm + 2 * ABUF;
    const uint32_t As_u = smem_u32(As), Bs_u = smem_u32(Bs);

    const int tid = threadIdx.x;
    const int wid = tid >> 5, lane = tid & 31;
    const int gid = lane >> 2, tig = lane & 3;
    const int wr = wid >> 2, wc = wid & 3;
    const int m0 = blockIdx.y * 128, n0 = blockIdx.x * 128;

    const int am = tid >> 1, ah = (tid & 1) * 16;
    const int bk = tid >> 3, bn = (tid & 7) * 16;

    const float* Arow = A + (size_t)(m0 + am) * DMODEL + ah;
    const float* Bcol = B + (size_t)bk * DEPTH + n0 + bn;

#define LOAD_CHUNK(c) do {                                                     \
        int _s = (c) & 1;                                                      \
        uint32_t _ad = As_u + (uint32_t)(_s * ABUF + am * PADA + ah) * 4;      \
        uint32_t _bd = Bs_u + (uint32_t)(_s * BBUF + bk * PADB + bn) * 4;      \
        const float* _ap = Arow + (c) * 32;                                    \
        const float* _bp = Bcol + (size_t)(c) * 32 * DEPTH;                    \
        _Pragma("unroll")                                                      \
        for (int _i = 0; _i < 4; _i++) {                                       \
            cp16(_ad + _i * 16, _ap + _i * 4);                                 \
            cp16(_bd + _i * 16, _bp + _i * 4);                                 \
        }                                                                      \
    } while (0)

    float c[4][4][4];
#pragma unroll
    for (int mt = 0; mt < 4; mt++)
#pragma unroll
        for (int nt = 0; nt < 4; nt++)
#pragma unroll
            for (int r = 0; r < 4; r++) c[mt][nt][r] = 0.f;

    LOAD_CHUNK(0);
    cp_commit();

#pragma unroll 1
    for (int ch = 0; ch < 32; ch++) {
        if (ch + 1 < 32) {
            LOAD_CHUNK(ch + 1);
            cp_commit();
            cp_wait1();
        } else {
            cp_wait0();
        }
        __syncthreads();

        const float* Ab = As + (ch & 1) * ABUF;
        const float* Bb = Bs + (ch & 1) * BBUF;
#pragma unroll
        for (int ks = 0; ks < 4; ks++) {
            const int k0 = ks * 8;
            uint32_t a[4][4], b[4][2];
#pragma unroll
            for (int mt = 0; mt < 4; mt++) {
                const float* ap = Ab + (wr * 64 + mt * 16 + gid) * PADA + k0 + tig;
                a[mt][0] = __float_as_uint(ap[0]);
                a[mt][1] = __float_as_uint(ap[8 * PADA]);
                a[mt][2] = __float_as_uint(ap[4]);
                a[mt][3] = __float_as_uint(ap[8 * PADA + 4]);
            }
#pragma unroll
            for (int nt = 0; nt < 4; nt++) {
                const float* bp = Bb + (k0 + tig) * PADB + wc * 32 + nt * 8 + gid;
                b[nt][0] = __float_as_uint(bp[0]);
                b[nt][1] = __float_as_uint(bp[4 * PADB]);
            }
#pragma unroll
            for (int mt = 0; mt < 4; mt++)
#pragma unroll
                for (int nt = 0; nt < 4; nt++)
                    mma_tf32(c[mt][nt][0], c[mt][nt][1], c[mt][nt][2], c[mt][nt][3],
                             a[mt][0], a[mt][1], a[mt][2], a[mt][3],
                             b[nt][0], b[nt][1]);
        }
        __syncthreads();
    }
#undef LOAD_CHUNK

    const bool round_out = (c_sel == 1 || c_sel == 2);
#pragma unroll
    for (int mt = 0; mt < 4; mt++) {
        const int row = m0 + wr * 64 + mt * 16 + gid;
#pragma unroll
        for (int nt = 0; nt < 4; nt++) {
            const int col = n0 + wc * 32 + nt * 8 + tig * 2;
            float2 bv = *(const float2*)&bias[col];
            float2 r0, r1;
            r0.x = c[mt][nt][0] + bv.x; r0.y = c[mt][nt][1] + bv.y;
            r1.x = c[mt][nt][2] + bv.x; r1.y = c[mt][nt][3] + bv.y;
            if (round_out) {
                r0.x = rna_tf32(r0.x); r0.y = rna_tf32(r0.y);
                r1.x = rna_tf32(r1.x); r1.y = rna_tf32(r1.y);
            }
            *(float2*)&C[(size_t)row * DEPTH + col] = r0;
            *(float2*)&C[(size_t)(row + 8) * DEPTH + col] = r1;
        }
    }
}

// ---------------------------------------------------------------------------
// Flash attention on m16n8k8 tf32 mma, fp32-accurate via hi/lo splits.
// CTA: 128 q rows of one (b,h). 8 warps x 16 rows. 64-key tiles,
// cp.async double-buffered K/V. P routed through smem (Q staging area reused).
// Smem strides: Q/P/K pad 68, V pad 72 (conflict-free fragment loads).
// ---------------------------------------------------------------------------
#define QP_PAD 68
#define V_PAD  72
#define SP_OFF  0                         // Q/P: 128 x 68
#define KS_OFF  (128 * QP_PAD)            // K: 2 x 64 x 68
#define VS_OFF  (KS_OFF + 2 * 64 * QP_PAD)// V: 2 x 64 x 72
#define ATTN_SMEM ((VS_OFF + 2 * 64 * V_PAD) * 4)   // 106496 B

__global__ __launch_bounds__(256) void flash_attn_tc_kernel()
{
    extern __shared__ float sm[];
    const int qt = (int)(gridDim.x - 1 - blockIdx.x);   // heavy tiles first
    const int h = blockIdx.y, b = blockIdx.z;
    const int tid = threadIdx.x;
    const int wq = tid >> 5, lane = tid & 31;
    const int gid = lane >> 2, tig = lane & 3;
    const int q0 = qt * 128;

    float* Sp = sm + SP_OFF;
    const uint32_t sm_u = smem_u32(sm);

    const int ntiles = 2 * qt + 2;

    // --- issue K/V tile 0 (cp.async) ---
    {
        const int k0 = 0;
#pragma unroll
        for (int i = 0; i < 4; i++) {
            int idx = i * 256 + tid;
            int row = idx >> 4, c4 = idx & 15;
            const float* kp = g_K + (size_t)(b * LK + k0 + row) * DEPTH + h * DK + c4 * 4;
            const float* vp = g_V + (size_t)(b * LK + k0 + row) * DEPTH + h * DK + c4 * 4;
            cp16(sm_u + (uint32_t)(KS_OFF + row * QP_PAD + c4 * 4) * 4, kp);
            cp16(sm_u + (uint32_t)(VS_OFF + row * V_PAD  + c4 * 4) * 4, vp);
        }
        cp_commit();
    }

    // --- stage Q (x fac) into Sp, then extract hi/lo A-fragments ---
    {
        const float fac = 0.125f;
#pragma unroll
        for (int i = 0; i < 8; i++) {
            int idx = i * 256 + tid;
            int row = idx >> 4, c4 = idx & 15;
            float4 v = *(const float4*)&g_Q[(size_t)(b * LQ + q0 + row) * DEPTH + h * DK + c4 * 4];
            float* d = &Sp[row * QP_PAD + c4 * 4];
            d[0] = v.x * fac; d[1] = v.y * fac; d[2] = v.z * fac; d[3] = v.w * fac;
        }
    }
    __syncthreads();

    uint32_t qhi[8][4], qlo[8][4];
    {
        const int r0 = wq * 16 + gid;
#pragma unroll
        for (int kc = 0; kc < 8; kc++) {
            float f0 = Sp[r0 * QP_PAD + kc * 8 + tig];
            float f1 = Sp[(r0 + 8) * QP_PAD + kc * 8 + tig];
            float f2 = Sp[r0 * QP_PAD + kc * 8 + tig + 4];
            float f3 = Sp[(r0 + 8) * QP_PAD + kc * 8 + tig + 4];
            float h0 = rna_tf32(f0), h1 = rna_tf32(f1), h2 = rna_tf32(f2), h3 = rna_tf32(f3);
            qhi[kc][0] = __float_as_uint(h0); qlo[kc][0] = __float_as_uint(rna_tf32(f0 - h0));
            qhi[kc][1] = __float_as_uint(h1); qlo[kc][1] = __float_as_uint(rna_tf32(f1 - h1));
            qhi[kc][2] = __float_as_uint(h2); qlo[kc][2] = __float_as_uint(rna_tf32(f2 - h2));
            qhi[kc][3] = __float_as_uint(h3); qlo[kc][3] = __float_as_uint(rna_tf32(f3 - h3));
        }
    }
    __syncthreads();   // Q fragments extracted; Sp free for P

    float o[8][4];
#pragma unroll
    for (int nc = 0; nc < 8; nc++)
#pragma unroll
        for (int r = 0; r < 4; r++) o[nc][r] = 0.f;
    float m0 = -1e30f, m1 = -1e30f, l0 = 0.f, l1 = 0.f;

    const int qrow0 = q0 + wq * 16 + gid;
    const int qrow1 = qrow0 + 8;
    float* Prow0 = &Sp[(wq * 16 + gid) * QP_PAD];
    float* Prow1 = Prow0 + 8 * QP_PAD;

#pragma unroll 1
    for (int kt = 0; kt < ntiles; kt++) {
        cp_wait0();
        __syncthreads();
        const int cur = kt & 1;
        if (kt + 1 < ntiles) {
            const int k1 = (kt + 1) * 64, nb = (kt + 1) & 1;
#pragma unroll
            for (int i = 0; i < 4; i++) {
                int idx = i * 256 + tid;
                int row = idx >> 4, c4 = idx & 15;
                const float* kp = g_K + (size_t)(b * LK + k1 + row) * DEPTH + h * DK + c4 * 4;
                const float* vp = g_V + (size_t)(b * LK + k1 + row) * DEPTH + h * DK + c4 * 4;
                cp16(sm_u + (uint32_t)(KS_OFF + nb * 64 * QP_PAD + row * QP_PAD + c4 * 4) * 4, kp);
                cp16(sm_u + (uint32_t)(VS_OFF + nb * 64 * V_PAD  + row * V_PAD  + c4 * 4) * 4, vp);
            }
            cp_commit();
        }

        const float* Ks = sm + KS_OFF + cur * 64 * QP_PAD;
        const float* Vs = sm + VS_OFF + cur * 64 * V_PAD;
        const int k0 = kt * 64;

        // ---- S = Q K^T (2-chain hi/lo, fp32-exact) ----
        float s[8][4];
#pragma unroll
        for (int nc = 0; nc < 8; nc++)
#pragma unroll
            for (int r = 0; r < 4; r++) s[nc][r] = 0.f;
#pragma unroll
        for (int kc = 0; kc < 8; kc++) {
#pragma unroll
            for (int nc = 0; nc < 8; nc++) {
                uint32_t b0 = __float_as_uint(Ks[(nc * 8 + gid) * QP_PAD + kc * 8 + tig]);
                uint32_t b1 = __float_as_uint(Ks[(nc * 8 + gid) * QP_PAD + kc * 8 + tig + 4]);
                mma_tf32(s[nc][0], s[nc][1], s[nc][2], s[nc][3],
                         qhi[kc][0], qhi[kc][1], qhi[kc][2], qhi[kc][3], b0, b1);
                mma_tf32(s[nc][0], s[nc][1], s[nc][2], s[nc][3],
                         qlo[kc][0], qlo[kc][1], qlo[kc][2], qlo[kc][3], b0, b1);
            }
        }

        // ---- causal mask (only the 2 diagonal tiles) ----
        if (kt >= 2 * qt) {
#pragma unroll
            for (int nc = 0; nc < 8; nc++) {
                int col = k0 + nc * 8 + 2 * tig;
                if (col > qrow0)     s[nc][0] = -1e30f;
                if (col + 1 > qrow0) s[nc][1] = -1e30f;
                if (col > qrow1)     s[nc][2] = -1e30f;
                if (col + 1 > qrow1) s[nc][3] = -1e30f;
            }
        }

        // ---- online softmax ----
        float mx0 = -1e30f, mx1 = -1e30f;
#pragma unroll
        for (int nc = 0; nc < 8; nc++) {
            mx0 = fmaxf(mx0, fmaxf(s[nc][0], s[nc][1]));
            mx1 = fmaxf(mx1, fmaxf(s[nc][2], s[nc][3]));
        }
        mx0 = fmaxf(mx0, __shfl_xor_sync(0xffffffffu, mx0, 1));
        mx0 = fmaxf(mx0, __shfl_xor_sync(0xffffffffu, mx0, 2));
        mx1 = fmaxf(mx1, __shfl_xor_sync(0xffffffffu, mx1, 1));
        mx1 = fmaxf(mx1, __shfl_xor_sync(0xffffffffu, mx1, 2));
        float mn0 = fmaxf(m0, mx0), mn1 = fmaxf(m1, mx1);
        float c0 = __expf(m0 - mn0), c1 = __expf(m1 - mn1);
        m0 = mn0; m1 = mn1;
        l0 *= c0; l1 *= c1;
#pragma unroll
        for (int nc = 0; nc < 8; nc++) {
            o[nc][0] *= c0; o[nc][1] *= c0;
            o[nc][2] *= c1; o[nc][3] *= c1;
        }
        float ls0 = 0.f, ls1 = 0.f;
#pragma unroll
        for (int nc = 0; nc < 8; nc++) {
            float p0 = __expf(s[nc][0] - mn0);
            float p1 = __expf(s[nc][1] - mn0);
            float p2 = __expf(s[nc][2] - mn1);
            float p3 = __expf(s[nc][3] - mn1);
            ls0 += p0 + p1; ls1 += p2 + p3;
            *(float2*)&Prow0[nc * 8 + 2 * tig] = make_float2(p0, p1);
            *(float2*)&Prow1[nc * 8 + 2 * tig] = make_float2(p2, p3);
        }
        l0 += ls0; l1 += ls1;
        __syncwarp();

        // ---- O += P V (2-chain hi/lo) ----
#pragma unroll
        for (int kc = 0; kc < 8; kc++) {
            float f0 = Prow0[kc * 8 + tig];
            float f1 = Prow1[kc * 8 + tig];
            float f2 = Prow0[kc * 8 + tig + 4];
            float f3 = Prow1[kc * 8 + tig + 4];
            float h0 = rna_tf32(f0), h1 = rna_tf32(f1), h2 = rna_tf32(f2), h3 = rna_tf32(f3);
            uint32_t phi0 = __float_as_uint(h0), plo0 = __float_as_uint(rna_tf32(f0 - h0));
            uint32_t phi1 = __float_as_uint(h1), plo1 = __float_as_uint(rna_tf32(f1 - h1));
            uint32_t phi2 = __float_as_uint(h2), plo2 = __float_as_uint(rna_tf32(f2 - h2));
            uint32_t phi3 = __float_as_uint(h3), plo3 = __float_as_uint(rna_tf32(f3 - h3));
#pragma unroll
            for (int nc = 0; nc < 8; nc++) {
                uint32_t b0 = __float_as_uint(Vs[(kc * 8 + tig) * V_PAD + nc * 8 + gid]);
                uint32_t b1 = __float_as_uint(Vs[(kc * 8 + tig + 4) * V_PAD + nc * 8 + gid]);
                mma_tf32(o[nc][0], o[nc][1], o[nc][2], o[nc][3],
                         phi0, phi1, phi2, phi3, b0, b1);
                mma_tf32(o[nc][0], o[nc][1], o[nc][2], o[nc][3],
                         plo0, plo1, plo2, plo3, b0, b1);
            }
        }
    }

    // ---- finalize: reduce l across tig, normalize, store (tf32-rounded) ----
    l0 += __shfl_xor_sync(0xffffffffu, l0, 1);
    l0 += __shfl_xor_sync(0xffffffffu, l0, 2);
    l1 += __shfl_xor_sync(0xffffffffu, l1, 1);
    l1 += __shfl_xor_sync(0xffffffffu, l1, 2);
    const float inv0 = 1.f / l0, inv1 = 1.f / l1;

    float* o0 = g_O + (size_t)(b * LQ + qrow0) * DEPTH + h * DK;
    float* o1 = g_O + (size_t)(b * LQ + qrow1) * DEPTH + h * DK;
#pragma unroll
    for (int nc = 0; nc < 8; nc++) {
        float2 r0 = make_float2(rna_tf32(o[nc][0] * inv0), rna_tf32(o[nc][1] * inv0));
        float2 r1 = make_float2(rna_tf32(o[nc][2] * inv1), rna_tf32(o[nc][3] * inv1));
        *(float2*)&o0[nc * 8 + 2 * tig] = r0;
        *(float2*)&o1[nc * 8 + 2 * tig] = r1;
    }
}

// ---------------------------------------------------------------------------
// Launch (order chosen so ncu -s 5 captures flash_attn_tc_kernel)
// ---------------------------------------------------------------------------
extern "C" void kernel_launch(void* const* d_in, const int* in_sizes, int n_in,
                              void* d_out, int out_size)
{
    const float* x  = (const float*)d_in[0];
    const float* y  = (const float*)d_in[1];
    // d_in[2] = mask (causal) — implicit
    const float* Wq = (const float*)d_in[3];
    const float* bq = (const float*)d_in[4];
    const float* Wk = (const float*)d_in[5];
    const float* bk = (const float*)d_in[6];
    const float* Wv = (const float*)d_in[7];
    const float* bv = (const float*)d_in[8];
    const float* Wo = (const float*)d_in[9];
    const float* bo = (const float*)d_in[10];
    float* out = (float*)d_out;

    cudaFuncSetAttribute(gemm_tc_kernel,
                         cudaFuncAttributeMaxDynamicSharedMemorySize, GEMM_SMEM);
    cudaFuncSetAttribute(flash_attn_tc_kernel,
                         cudaFuncAttributeMaxDynamicSharedMemorySize, ATTN_SMEM);

    round_xy_kernel<<<dim3(4096, 2), 256>>>(x, y);                     // 0
    round_w_kernel<<<dim3(1024, 4), 256>>>(Wq, Wk, Wv, Wo);            // 1

    dim3 ggrid(DEPTH / 128, MROWS / 128);
    gemm_tc_kernel<<<ggrid, 256, GEMM_SMEM>>>(bq, nullptr, 0, 0, 0);   // 2: -> g_Q
    gemm_tc_kernel<<<ggrid, 256, GEMM_SMEM>>>(bk, nullptr, 1, 1, 1);   // 3: -> g_K (tf32)
    gemm_tc_kernel<<<ggrid, 256, GEMM_SMEM>>>(bv, nullptr, 1, 2, 2);   // 4: -> g_V (tf32)

    dim3 agrid(LQ / 128, DHEAD, NB);
    flash_attn_tc_kernel<<<agrid, 256, ATTN_SMEM>>>();                 // 5: -> g_O

    gemm_tc_kernel<<<ggrid, 256, GEMM_SMEM>>>(bo, out, 2, 3, 3);       // 6: -> out
}

// round 8
// speedup vs baseline: 2.9610x; 1.0388x over previous
#include <cuda_runtime.h>
#include <cstdint>
#include <cstddef>

#define NB      2
#define LQ      2048
#define LK      2048
#define DMODEL  1024
#define DK      64
#define DHEAD   16
#define DEPTH   1024
#define MROWS   4096

// Scratch (__device__ globals; allocation-free rule)
__device__ float g_Q[(size_t)MROWS * DEPTH];
__device__ float g_K[(size_t)MROWS * DEPTH];   // [token][1024], tf32-rounded
__device__ float g_V[(size_t)MROWS * DEPTH];   // TRANSPOSED: [b][h][64 dim][2048 key], tf32-rounded
__device__ float g_O[(size_t)MROWS * DEPTH];   // tf32-rounded
__device__ float g_Xc[(size_t)MROWS * DMODEL];
__device__ float g_Yc[(size_t)MROWS * DMODEL];
__device__ float g_Wc[4][(size_t)DMODEL * DEPTH];  // tf32-rounded W^T: [n][k]

// ---------------------------------------------------------------------------
// Helpers
// ---------------------------------------------------------------------------
__device__ __forceinline__ uint32_t smem_u32(const void* p) {
    uint32_t a;
    asm("{ .reg .u64 t; cvta.to.shared.u64 t, %1; cvt.u32.u64 %0, t; }"
        : "=r"(a) : "l"(p));
    return a;
}
__device__ __forceinline__ float rna_tf32(float x) {
    float r; asm("cvt.rna.tf32.f32 %0, %1;" : "=f"(r) : "f"(x)); return r;
}
__device__ __forceinline__ void cp16(uint32_t dst, const void* src) {
    asm volatile("cp.async.cg.shared.global [%0], [%1], 16;" :: "r"(dst), "l"(src));
}
__device__ __forceinline__ void cp_commit() { asm volatile("cp.async.commit_group;"); }
__device__ __forceinline__ void cp_wait1()  { asm volatile("cp.async.wait_group 1;" ::: "memory"); }
__device__ __forceinline__ void cp_wait0()  { asm volatile("cp.async.wait_group 0;" ::: "memory"); }

// m16n8k8 tf32 mma: D = A*B + D
__device__ __forceinline__ void mma_tf32(float& c0, float& c1, float& c2, float& c3,
                                         uint32_t a0, uint32_t a1, uint32_t a2, uint32_t a3,
                                         uint32_t b0, uint32_t b1) {
    asm volatile("mma.sync.aligned.m16n8k8.row.col.f32.tf32.tf32.f32 "
                 "{%0,%1,%2,%3}, {%4,%5,%6,%7}, {%8,%9}, {%0,%1,%2,%3};"
                 : "+f"(c0), "+f"(c1), "+f"(c2), "+f"(c3)
                 : "r"(a0), "r"(a1), "r"(a2), "r"(a3), "r"(b0), "r"(b1));
}
// ldmatrix x4: four 8x8 b16 matrices (= four 8x4 f32 fragments)
__device__ __forceinline__ void ldmx4(uint32_t* d, uint32_t addr) {
    asm volatile("ldmatrix.sync.aligned.m8n8.x4.shared.b16 {%0,%1,%2,%3}, [%4];"
                 : "=r"(d[0]), "=r"(d[1]), "=r"(d[2]), "=r"(d[3]) : "r"(addr));
}

// ---------------------------------------------------------------------------
// Prepass 1: tf32-round x/y
// ---------------------------------------------------------------------------
__global__ __launch_bounds__(256) void round_xy_kernel(const float* __restrict__ x,
                                                       const float* __restrict__ y) {
    const float* in = blockIdx.y ? y : x;
    float* out = blockIdx.y ? g_Yc : g_Xc;
    size_t i = (size_t)blockIdx.x * 256 + threadIdx.x;
    float4 v = ((const float4*)in)[i];
    v.x = rna_tf32(v.x); v.y = rna_tf32(v.y);
    v.z = rna_tf32(v.z); v.w = rna_tf32(v.w);
    ((float4*)out)[i] = v;
}
// ---------------------------------------------------------------------------
// Prepass 2: W[k][n] -> g_Wc[widx][n][k], tf32-rounded
// ---------------------------------------------------------------------------
__global__ __launch_bounds__(256) void wtrans_kernel(const float* __restrict__ w0,
                                                     const float* __restrict__ w1,
                                                     const float* __restrict__ w2,
                                                     const float* __restrict__ w3) {
    __shared__ float tile[32][33];
    const float* W;
    switch (blockIdx.z) { case 0: W = w0; break; case 1: W = w1; break;
                          case 2: W = w2; break; default: W = w3; break; }
    const int tx = threadIdx.x, ty = threadIdx.y;     // 32 x 8
    const int bx = blockIdx.x, by = blockIdx.y;       // n-tile, k-tile
#pragma unroll
    for (int i = 0; i < 4; i++)
        tile[ty + 8 * i][tx] = rna_tf32(W[(size_t)(by * 32 + ty + 8 * i) * DEPTH + bx * 32 + tx]);
    __syncthreads();
    float* out = g_Wc[blockIdx.z];
#pragma unroll
    for (int i = 0; i < 4; i++)
        out[(size_t)(bx * 32 + ty + 8 * i) * DMODEL + by * 32 + tx] = tile[tx][ty + 8 * i];
}

// ---------------------------------------------------------------------------
// tf32 mma.sync GEMM with ldmatrix fragments.
// C[4096,1024] = A[m][k] @ Wc[n][k]^T + bias. CTA 128x128, BK=32, dbl-buffer.
// Smem A,B both [128][36]. c_sel==2 writes V transposed [b][h][dim][key].
// ---------------------------------------------------------------------------
#define PAD  36
#define TBUF (128 * PAD)
#define GEMM_SMEM (4 * TBUF * 4)

__global__ __launch_bounds__(256) void gemm_tc_kernel(
    const float* __restrict__ bias, float* __restrict__ Cout,
    int a_sel, int widx, int c_sel)
{
    extern __shared__ float sm[];
    const float* A = (a_sel == 0) ? g_Xc : (a_sel == 1) ? g_Yc : g_O;
    const float* B = g_Wc[widx];
    float* C;
    switch (c_sel) { case 0: C = g_Q; break; case 1: C = g_K; break;
                     case 2: C = g_V; break; default: C = Cout; break; }

    float* As = sm;                 // 2 x TBUF
    float* Bs = sm + 2 * TBUF;      // 2 x TBUF
    const uint32_t As_u = smem_u32(As), Bs_u = smem_u32(Bs);

    const int tid = threadIdx.x;
    const int wid = tid >> 5, lane = tid & 31;
    const int gid = lane >> 2, tig = lane & 3;
    const int g8 = lane >> 3, r8 = lane & 7;
    const int wr = wid >> 2, wc = wid & 3;
    const int m0 = blockIdx.y * 128, n0 = blockIdx.x * 128;

    // cp.async mapping: 2 threads per row, 16 floats each
    const int lrow = tid >> 1, lofs = (tid & 1) * 16;
    const float* Arow = A + (size_t)(m0 + lrow) * DMODEL + lofs;
    const float* Brow = B + (size_t)(n0 + lrow) * DMODEL + lofs;

    // ldmatrix per-thread fragment bases (float offsets within a buffer)
    // A frags: row = wr*64 + mt*16 + r8 + (g8&1)*8 ; col = ks*8 + (g8>>1)*4
    const uint32_t aA = As_u + (uint32_t)((wr * 64 + r8 + (g8 & 1) * 8) * PAD + (g8 >> 1) * 4) * 4;
    // B frags: row = wc*32 + ntp*16 + r8 + (g8>>1)*8 ; col = ks*8 + (g8&1)*4
    const uint32_t aB = Bs_u + (uint32_t)((wc * 32 + r8 + (g8 >> 1) * 8) * PAD + (g8 & 1) * 4) * 4;

#define LOAD_CHUNK(c) do {                                                     \
        int _s = (c) & 1;                                                      \
        uint32_t _ad = As_u + (uint32_t)(_s * TBUF + lrow * PAD + lofs) * 4;   \
        uint32_t _bd = Bs_u + (uint32_t)(_s * TBUF + lrow * PAD + lofs) * 4;   \
        const float* _ap = Arow + (c) * 32;                                    \
        const float* _bp = Brow + (c) * 32;                                    \
        _Pragma("unroll")                                                      \
        for (int _i = 0; _i < 4; _i++) {                                       \
            cp16(_ad + _i * 16, _ap + _i * 4);                                 \
            cp16(_bd + _i * 16, _bp + _i * 4);                                 \
        }                                                                      \
    } while (0)

    float c[4][4][4];
#pragma unroll
    for (int mt = 0; mt < 4; mt++)
#pragma unroll
        for (int nt = 0; nt < 4; nt++)
#pragma unroll
            for (int r = 0; r < 4; r++) c[mt][nt][r] = 0.f;

    LOAD_CHUNK(0);
    cp_commit();

#pragma unroll 1
    for (int ch = 0; ch < 32; ch++) {
        if (ch + 1 < 32) {
            LOAD_CHUNK(ch + 1);
            cp_commit();
            cp_wait1();
        } else {
            cp_wait0();
        }
        __syncthreads();

        const uint32_t Ab = aA + (uint32_t)((ch & 1) * TBUF) * 4;
        const uint32_t Bb = aB + (uint32_t)((ch & 1) * TBUF) * 4;
#pragma unroll
        for (int ks = 0; ks < 4; ks++) {
            uint32_t a[4][4], b[4][2];
#pragma unroll
            for (int mt = 0; mt < 4; mt++)
                ldmx4(a[mt], Ab + (uint32_t)(mt * 16 * PAD + ks * 8) * 4);
#pragma unroll
            for (int ntp = 0; ntp < 2; ntp++) {
                uint32_t t[4];
                ldmx4(t, Bb + (uint32_t)(ntp * 16 * PAD + ks * 8) * 4);
                b[2 * ntp][0] = t[0]; b[2 * ntp][1] = t[1];
                b[2 * ntp + 1][0] = t[2]; b[2 * ntp + 1][1] = t[3];
            }
#pragma unroll
            for (int mt = 0; mt < 4; mt++)
#pragma unroll
                for (int nt = 0; nt < 4; nt++)
                    mma_tf32(c[mt][nt][0], c[mt][nt][1], c[mt][nt][2], c[mt][nt][3],
                             a[mt][0], a[mt][1], a[mt][2], a[mt][3],
                             b[nt][0], b[nt][1]);
        }
        __syncthreads();
    }
#undef LOAD_CHUNK

    if (c_sel == 2) {
        // V: write transposed [b][h][dim][key], tf32-rounded
#pragma unroll
        for (int mt = 0; mt < 4; mt++) {
            const int row = m0 + wr * 64 + mt * 16 + gid;     // token
#pragma unroll
            for (int nt = 0; nt < 4; nt++) {
                const int col = n0 + wc * 32 + nt * 8 + tig * 2;   // dim global
                float2 bv = *(const float2*)&bias[col];
                const int bb = row >> 11, key = row & 2047;
                const int hh = col >> 6, dd = col & 63;
                float* vb = C + (((size_t)bb * DHEAD + hh) * DK + dd) * LK;
                vb[key]            = rna_tf32(c[mt][nt][0] + bv.x);
                vb[LK + key]       = rna_tf32(c[mt][nt][1] + bv.y);
                vb[key + 8]        = rna_tf32(c[mt][nt][2] + bv.x);
                vb[LK + key + 8]   = rna_tf32(c[mt][nt][3] + bv.y);
            }
        }
    } else {
        const bool round_out = (c_sel == 1);
#pragma unroll
        for (int mt = 0; mt < 4; mt++) {
            const int row = m0 + wr * 64 + mt * 16 + gid;
#pragma unroll
            for (int nt = 0; nt < 4; nt++) {
                const int col = n0 + wc * 32 + nt * 8 + tig * 2;
                float2 bv = *(const float2*)&bias[col];
                float2 r0, r1;
                r0.x = c[mt][nt][0] + bv.x; r0.y = c[mt][nt][1] + bv.y;
                r1.x = c[mt][nt][2] + bv.x; r1.y = c[mt][nt][3] + bv.y;
                if (round_out) {
                    r0.x = rna_tf32(r0.x); r0.y = rna_tf32(r0.y);
                    r1.x = rna_tf32(r1.x); r1.y = rna_tf32(r1.y);
                }
                *(float2*)&C[(size_t)row * DEPTH + col] = r0;
                *(float2*)&C[(size_t)(row + 8) * DEPTH + col] = r1;
            }
        }
    }
}

// ---------------------------------------------------------------------------
// Flash attention, mma.sync + ldmatrix fragments, hi/lo fp32 accuracy.
// Smem: Q/P [128][68]; K 2x[64 key][68]; V 2x[64 dim][68] (V global transposed).
// ---------------------------------------------------------------------------
#define APAD   68
#define SP_OFF 0
#define KS_OFF (128 * APAD)
#define VS_OFF (KS_OFF + 2 * 64 * APAD)
#define ATTN_SMEM ((VS_OFF + 2 * 64 * APAD) * 4)

__global__ __launch_bounds__(256) void flash_attn_tc_kernel()
{
    extern __shared__ float sm[];
    const int qt = (int)(gridDim.x - 1 - blockIdx.x);   // heavy tiles first
    const int h = blockIdx.y, b = blockIdx.z;
    const int tid = threadIdx.x;
    const int wq = tid >> 5, lane = tid & 31;
    const int gid = lane >> 2, tig = lane & 3;
    const int g8 = lane >> 3, r8 = lane & 7;
    const int q0 = qt * 128;

    float* Sp = sm + SP_OFF;
    const uint32_t sm_u = smem_u32(sm);
    const float* Vt = g_V + ((size_t)b * DHEAD + h) * DK * LK;

    const int ntiles = 2 * qt + 2;

    // ldmatrix fragment bases
    // A-frag (Q / P): row = wq*16 + r8 + (g8&1)*8 ; col = kc*8 + (g8>>1)*4
    const uint32_t aSP = sm_u + (uint32_t)(SP_OFF + (wq * 16 + r8 + (g8 & 1) * 8) * APAD + (g8 >> 1) * 4) * 4;
    // B-frag (K / V): row = ncp*16 + r8 + (g8>>1)*8 ; col = kc*8 + (g8&1)*4
    const uint32_t bOFS = (uint32_t)((r8 + (g8 >> 1) * 8) * APAD + (g8 & 1) * 4) * 4;
    const uint32_t aK = sm_u + (uint32_t)KS_OFF * 4 + bOFS;
    const uint32_t aV = sm_u + (uint32_t)VS_OFF * 4 + bOFS;

    // --- issue K/V tile 0 ---
    {
#pragma unroll
        for (int i = 0; i < 4; i++) {
            int idx = i * 256 + tid;
            int row = idx >> 4, c4 = idx & 15;
            const float* kp = g_K + (size_t)(b * LK + row) * DEPTH + h * DK + c4 * 4;
            const float* vp = Vt + (size_t)row * LK + c4 * 4;      // row=dim, first 64 keys
            cp16(sm_u + (uint32_t)(KS_OFF + row * APAD + c4 * 4) * 4, kp);
            cp16(sm_u + (uint32_t)(VS_OFF + row * APAD + c4 * 4) * 4, vp);
        }
        cp_commit();
    }

    // --- stage Q (x fac) into Sp, extract hi/lo A-fragments via ldmatrix ---
    {
        const float fac = 0.125f;
#pragma unroll
        for (int i = 0; i < 8; i++) {
            int idx = i * 256 + tid;
            int row = idx >> 4, c4 = idx & 15;
            float4 v = *(const float4*)&g_Q[(size_t)(b * LQ + q0 + row) * DEPTH + h * DK + c4 * 4];
            float* d = &Sp[row * APAD + c4 * 4];
            d[0] = v.x * fac; d[1] = v.y * fac; d[2] = v.z * fac; d[3] = v.w * fac;
        }
    }
    __syncthreads();

    uint32_t qhi[8][4], qlo[8][4];
#pragma unroll
    for (int kc = 0; kc < 8; kc++) {
        uint32_t t[4];
        ldmx4(t, aSP + (uint32_t)(kc * 8) * 4);
#pragma unroll
        for (int j = 0; j < 4; j++) {
            float f = __uint_as_float(t[j]);
            float hi = rna_tf32(f);
            qhi[kc][j] = __float_as_uint(hi);
            qlo[kc][j] = __float_as_uint(rna_tf32(f - hi));
        }
    }
    __syncthreads();   // Sp free for P

    float o[8][4];
#pragma unroll
    for (int nc = 0; nc < 8; nc++)
#pragma unroll
        for (int r = 0; r < 4; r++) o[nc][r] = 0.f;
    float m0 = -1e30f, m1 = -1e30f, l0 = 0.f, l1 = 0.f;

    const int qrow0 = q0 + wq * 16 + gid;
    const int qrow1 = qrow0 + 8;
    float* Prow0 = &Sp[(wq * 16 + gid) * APAD];
    float* Prow1 = Prow0 + 8 * APAD;

#pragma unroll 1
    for (int kt = 0; kt < ntiles; kt++) {
        cp_wait0();
        __syncthreads();
        const int cur = kt & 1;
        if (kt + 1 < ntiles) {
            const int k1 = (kt + 1) * 64, nb = (kt + 1) & 1;
#pragma unroll
            for (int i = 0; i < 4; i++) {
                int idx = i * 256 + tid;
                int row = idx >> 4, c4 = idx & 15;
                const float* kp = g_K + (size_t)(b * LK + k1 + row) * DEPTH + h * DK + c4 * 4;
                const float* vp = Vt + (size_t)row * LK + k1 + c4 * 4;
                cp16(sm_u + (uint32_t)(KS_OFF + nb * 64 * APAD + row * APAD + c4 * 4) * 4, kp);
                cp16(sm_u + (uint32_t)(VS_OFF + nb * 64 * APAD + row * APAD + c4 * 4) * 4, vp);
            }
            cp_commit();
        }

        const uint32_t Kb = aK + (uint32_t)(cur * 64 * APAD) * 4;
        const uint32_t Vb = aV + (uint32_t)(cur * 64 * APAD) * 4;
        const int k0 = kt * 64;

        // ---- S = Q K^T (hi/lo chains) ----
        float s[8][4];
#pragma unroll
        for (int nc = 0; nc < 8; nc++)
#pragma unroll
            for (int r = 0; r < 4; r++) s[nc][r] = 0.f;
#pragma unroll
        for (int kc = 0; kc < 8; kc++) {
#pragma unroll
            for (int ncp = 0; ncp < 4; ncp++) {
                uint32_t t[4];
                ldmx4(t, Kb + (uint32_t)(ncp * 16 * APAD + kc * 8) * 4);
                const int n0i = 2 * ncp, n1i = 2 * ncp + 1;
                mma_tf32(s[n0i][0], s[n0i][1], s[n0i][2], s[n0i][3],
                         qhi[kc][0], qhi[kc][1], qhi[kc][2], qhi[kc][3], t[0], t[1]);
                mma_tf32(s[n0i][0], s[n0i][1], s[n0i][2], s[n0i][3],
                         qlo[kc][0], qlo[kc][1], qlo[kc][2], qlo[kc][3], t[0], t[1]);
                mma_tf32(s[n1i][0], s[n1i][1], s[n1i][2], s[n1i][3],
                         qhi[kc][0], qhi[kc][1], qhi[kc][2], qhi[kc][3], t[2], t[3]);
                mma_tf32(s[n1i][0], s[n1i][1], s[n1i][2], s[n1i][3],
                         qlo[kc][0], qlo[kc][1], qlo[kc][2], qlo[kc][3], t[2], t[3]);
            }
        }

        // ---- causal mask (diagonal tiles only) ----
        if (kt >= 2 * qt) {
#pragma unroll
            for (int nc = 0; nc < 8; nc++) {
                int col = k0 + nc * 8 + 2 * tig;
                if (col > qrow0)     s[nc][0] = -1e30f;
                if (col + 1 > qrow0) s[nc][1] = -1e30f;
                if (col > qrow1)     s[nc][2] = -1e30f;
                if (col + 1 > qrow1) s[nc][3] = -1e30f;
            }
        }

        // ---- online softmax ----
        float mx0 = -1e30f, mx1 = -1e30f;
#pragma unroll
        for (int nc = 0; nc < 8; nc++) {
            mx0 = fmaxf(mx0, fmaxf(s[nc][0], s[nc][1]));
            mx1 = fmaxf(mx1, fmaxf(s[nc][2], s[nc][3]));
        }
        mx0 = fmaxf(mx0, __shfl_xor_sync(0xffffffffu, mx0, 1));
        mx0 = fmaxf(mx0, __shfl_xor_sync(0xffffffffu, mx0, 2));
        mx1 = fmaxf(mx1, __shfl_xor_sync(0xffffffffu, mx1, 1));
        mx1 = fmaxf(mx1, __shfl_xor_sync(0xffffffffu, mx1, 2));
        float mn0 = fmaxf(m0, mx0), mn1 = fmaxf(m1, mx1);
        float c0 = __expf(m0 - mn0), c1 = __expf(m1 - mn1);
        m0 = mn0; m1 = mn1;
        l0 *= c0; l1 *= c1;
#pragma unroll
        for (int nc = 0; nc < 8; nc++) {
            o[nc][0] *= c0; o[nc][1] *= c0;
            o[nc][2] *= c1; o[nc][3] *= c1;
        }
        float ls0 = 0.f, ls1 = 0.f;
#pragma unroll
        for (int nc = 0; nc < 8; nc++) {
            float p0 = __expf(s[nc][0] - mn0);
            float p1 = __expf(s[nc][1] - mn0);
            float p2 = __expf(s[nc][2] - mn1);
            float p3 = __expf(s[nc][3] - mn1);
            ls0 += p0 + p1; ls1 += p2 + p3;
            *(float2*)&Prow0[nc * 8 + 2 * tig] = make_float2(p0, p1);
            *(float2*)&Prow1[nc * 8 + 2 * tig] = make_float2(p2, p3);
        }
        l0 += ls0; l1 += ls1;
        __syncwarp();

        // ---- O += P V (hi/lo chains), P via ldmatrix ----
#pragma unroll
        for (int kc = 0; kc < 8; kc++) {
            uint32_t pt[4];
            ldmx4(pt, aSP + (uint32_t)(kc * 8) * 4);
            uint32_t phi[4], plo[4];
#pragma unroll
            for (int j = 0; j < 4; j++) {
                float f = __uint_as_float(pt[j]);
                float hi = rna_tf32(f);
                phi[j] = __float_as_uint(hi);
                plo[j] = __float_as_uint(rna_tf32(f - hi));
            }
#pragma unroll
            for (int ncp = 0; ncp < 4; ncp++) {
                uint32_t t[4];
                ldmx4(t, Vb + (uint32_t)(ncp * 16 * APAD + kc * 8) * 4);
                const int n0i = 2 * ncp, n1i = 2 * ncp + 1;
                mma_tf32(o[n0i][0], o[n0i][1], o[n0i][2], o[n0i][3],
                         phi[0], phi[1], phi[2], phi[3], t[0], t[1]);
                mma_tf32(o[n0i][0], o[n0i][1], o[n0i][2], o[n0i][3],
                         plo[0], plo[1], plo[2], plo[3], t[0], t[1]);
                mma_tf32(o[n1i][0], o[n1i][1], o[n1i][2], o[n1i][3],
                         phi[0], phi[1], phi[2], phi[3], t[2], t[3]);
                mma_tf32(o[n1i][0], o[n1i][1], o[n1i][2], o[n1i][3],
                         plo[0], plo[1], plo[2], plo[3], t[2], t[3]);
            }
        }
        __syncthreads();   // P consumed before next tile overwrites Sp? (Sp reused per tile)
    }

    // ---- finalize ----
    l0 += __shfl_xor_sync(0xffffffffu, l0, 1);
    l0 += __shfl_xor_sync(0xffffffffu, l0, 2);
    l1 += __shfl_xor_sync(0xffffffffu, l1, 1);
    l1 += __shfl_xor_sync(0xffffffffu, l1, 2);
    const float inv0 = 1.f / l0, inv1 = 1.f / l1;

    float* o0 = g_O + (size_t)(b * LQ + qrow0) * DEPTH + h * DK;
    float* o1 = g_O + (size_t)(b * LQ + qrow1) * DEPTH + h * DK;
#pragma unroll
    for (int nc = 0; nc < 8; nc++) {
        float2 r0 = make_float2(rna_tf32(o[nc][0] * inv0), rna_tf32(o[nc][1] * inv0));
        float2 r1 = make_float2(rna_tf32(o[nc][2] * inv1), rna_tf32(o[nc][3] * inv1));
        *(float2*)&o0[nc * 8 + 2 * tig] = r0;
        *(float2*)&o1[nc * 8 + 2 * tig] = r1;
    }
}

// ---------------------------------------------------------------------------
// Launch (attention is launch index 5 for ncu -s 5)
// ---------------------------------------------------------------------------
extern "C" void kernel_launch(void* const* d_in, const int* in_sizes, int n_in,
                              void* d_out, int out_size)
{
    const float* x  = (const float*)d_in[0];
    const float* y  = (const float*)d_in[1];
    // d_in[2] = causal mask — implicit
    const float* Wq = (const float*)d_in[3];
    const float* bq = (const float*)d_in[4];
    const float* Wk = (const float*)d_in[5];
    const float* bk = (const float*)d_in[6];
    const float* Wv = (const float*)d_in[7];
    const float* bv = (const float*)d_in[8];
    const float* Wo = (const float*)d_in[9];
    const float* bo = (const float*)d_in[10];
    float* out = (float*)d_out;

    cudaFuncSetAttribute(gemm_tc_kernel,
                         cudaFuncAttributeMaxDynamicSharedMemorySize, GEMM_SMEM);
    cudaFuncSetAttribute(flash_attn_tc_kernel,
                         cudaFuncAttributeMaxDynamicSharedMemorySize, ATTN_SMEM);

    round_xy_kernel<<<dim3(4096, 2), 256>>>(x, y);                     // 0
    wtrans_kernel<<<dim3(32, 32, 4), dim3(32, 8)>>>(Wq, Wk, Wv, Wo);   // 1

    dim3 ggrid(DEPTH / 128, MROWS / 128);
    gemm_tc_kernel<<<ggrid, 256, GEMM_SMEM>>>(bq, nullptr, 0, 0, 0);   // 2: -> g_Q
    gemm_tc_kernel<<<ggrid, 256, GEMM_SMEM>>>(bk, nullptr, 1, 1, 1);   // 3: -> g_K (tf32)
    gemm_tc_kernel<<<ggrid, 256, GEMM_SMEM>>>(bv, nullptr, 1, 2, 2);   // 4: -> g_V transposed (tf32)

    dim3 agrid(LQ / 128, DHEAD, NB);
    flash_attn_tc_kernel<<<agrid, 256, ATTN_SMEM>>>();                 // 5: -> g_O

    gemm_tc_kernel<<<ggrid, 256, GEMM_SMEM>>>(bo, out, 2, 3, 3);       // 6: -> out
}